// round 16
// baseline (speedup 1.0000x reference)
#include <cuda_runtime.h>
#include <cuda_fp16.h>
#include <math.h>
#include <stdint.h>

// Problem constants
#define TOK   8192
#define DDIM  1024
#define FDIM  2048
#define NEXP  8
#define TOPK  2

#define BK    64
#define NW4   ((size_t)NEXP * DDIM * FDIM / 4)

// ---------------------------------------------------------------------------
// Scratch
// ---------------------------------------------------------------------------
__device__ int   g_count[NEXP];
__device__ int   g_rows [NEXP * TOK];
__device__ int   g_slot [NEXP * TOK];
__device__ float g_gate [TOK * TOPK];
__device__ __align__(16) float  g_Y  [(size_t)TOK * TOPK * DDIM];
__device__ __align__(16) __half g_X  [(size_t)TOK * DDIM];
__device__ __align__(16) __half g_W1h[(size_t)NEXP * DDIM * FDIM];
__device__ __align__(16) __half g_W3h[(size_t)NEXP * DDIM * FDIM];
__device__ __align__(16) __half g_W2h[(size_t)NEXP * FDIM * DDIM];
__device__ __align__(16) __half g_Hh [(size_t)NEXP * TOK * FDIM];

// ---------------------------------------------------------------------------
// helpers
// ---------------------------------------------------------------------------
__device__ __forceinline__ uint32_t smem_u32(const void* p) {
    uint32_t a;
    asm("{ .reg .u64 t; cvta.to.shared.u64 t, %1; cvt.u32.u64 %0, t; }"
        : "=r"(a) : "l"(p));
    return a;
}

__device__ __forceinline__ void mmah(float c[4], const uint32_t a[4],
                                     uint32_t b0, uint32_t b1) {
    asm volatile(
        "mma.sync.aligned.m16n8k16.row.col.f32.f16.f16.f32 "
        "{%0,%1,%2,%3}, {%4,%5,%6,%7}, {%8,%9}, {%0,%1,%2,%3};"
        : "+f"(c[0]), "+f"(c[1]), "+f"(c[2]), "+f"(c[3])
        : "r"(a[0]), "r"(a[1]), "r"(a[2]), "r"(a[3]), "r"(b0), "r"(b1));
}

__device__ __forceinline__ void ldsm4(uint32_t r[4], uint32_t addr) {
    asm volatile("ldmatrix.sync.aligned.m8n8.x4.shared.b16 {%0,%1,%2,%3}, [%4];"
                 : "=r"(r[0]), "=r"(r[1]), "=r"(r[2]), "=r"(r[3]) : "r"(addr));
}

__device__ __forceinline__ void ldsm4t(uint32_t r[4], uint32_t addr) {
    asm volatile("ldmatrix.sync.aligned.m8n8.x4.trans.shared.b16 {%0,%1,%2,%3}, [%4];"
                 : "=r"(r[0]), "=r"(r[1]), "=r"(r[2]), "=r"(r[3]) : "r"(addr));
}

#define CP16(dst, src) \
    asm volatile("cp.async.cg.shared.global [%0], [%1], 16;" \
                 :: "r"(dst), "l"(src) : "memory")
#define CPCOMMIT() asm volatile("cp.async.commit_group;" ::: "memory")
#define CPWAIT2()  asm volatile("cp.async.wait_group 2;" ::: "memory")

// ---------------------------------------------------------------------------
// 0) zero expert counters
// ---------------------------------------------------------------------------
__global__ void zero_counts_kernel() {
    if (threadIdx.x < NEXP) g_count[threadIdx.x] = 0;
}

// ---------------------------------------------------------------------------
// 1) aux: router (blocks 0..1023) + weight fp16 conversion (blocks >= 1024)
// ---------------------------------------------------------------------------
__global__ __launch_bounds__(256) void aux_kernel(const float* __restrict__ x,
                                                  const float* __restrict__ Wg,
                                                  const float4* __restrict__ W1,
                                                  const float4* __restrict__ W3,
                                                  const float4* __restrict__ W2) {
    if (blockIdx.x < 1024) {
        const int warp = (blockIdx.x * 256 + threadIdx.x) >> 5;
        const int lane = threadIdx.x & 31;

        const float* xr = x + (size_t)warp * DDIM;
        __half* xh = g_X + (size_t)warp * DDIM;
        float acc[NEXP];
#pragma unroll
        for (int e = 0; e < NEXP; e++) acc[e] = 0.f;

        for (int d = lane; d < DDIM; d += 32) {
            const float xv = xr[d];
            xh[d] = __float2half_rn(xv);
            const float4 w0 = *reinterpret_cast<const float4*>(Wg + (size_t)d * NEXP);
            const float4 w1 = *reinterpret_cast<const float4*>(Wg + (size_t)d * NEXP + 4);
            acc[0] += xv * w0.x; acc[1] += xv * w0.y; acc[2] += xv * w0.z; acc[3] += xv * w0.w;
            acc[4] += xv * w1.x; acc[5] += xv * w1.y; acc[6] += xv * w1.z; acc[7] += xv * w1.w;
        }
#pragma unroll
        for (int off = 16; off > 0; off >>= 1) {
#pragma unroll
            for (int e = 0; e < NEXP; e++)
                acc[e] += __shfl_xor_sync(0xFFFFFFFFu, acc[e], off);
        }

        if (lane == 0) {
            int i0 = 0; float v0 = acc[0];
#pragma unroll
            for (int e = 1; e < NEXP; e++) if (acc[e] > v0) { v0 = acc[e]; i0 = e; }
            int i1 = -1; float v1 = -INFINITY;
#pragma unroll
            for (int e = 0; e < NEXP; e++)
                if (e != i0 && acc[e] > v1) { v1 = acc[e]; i1 = e; }

            const float e1 = expf(v1 - v0);
            const float inv = 1.f / (1.f + e1);
            g_gate[warp * 2 + 0] = inv;
            g_gate[warp * 2 + 1] = e1 * inv;

            int p0 = atomicAdd(&g_count[i0], 1);
            g_rows[i0 * TOK + p0] = warp;
            g_slot[i0 * TOK + p0] = warp * 2;
            int p1 = atomicAdd(&g_count[i1], 1);
            g_rows[i1 * TOK + p1] = warp;
            g_slot[i1 * TOK + p1] = warp * 2 + 1;
        }
    } else {
        const size_t total = 3 * NW4;
        const size_t stride = (size_t)2048 * 256;
        for (size_t i = (size_t)(blockIdx.x - 1024) * 256 + threadIdx.x;
             i < total; i += stride) {
            const float4* src; __half2* dst; size_t off;
            if (i < NW4)            { src = W1; dst = (__half2*)g_W1h; off = i; }
            else if (i < 2 * NW4)   { src = W3; dst = (__half2*)g_W3h; off = i - NW4; }
            else                    { src = W2; dst = (__half2*)g_W2h; off = i - 2 * NW4; }
            float4 v = src[off];
            dst[off * 2]     = __floats2half2_rn(v.x, v.y);
            dst[off * 2 + 1] = __floats2half2_rn(v.z, v.w);
        }
    }
}

// ---------------------------------------------------------------------------
// 2) Grouped dual GEMM + SwiGLU, fp16 HMMA. Block 256x64, 256 threads,
//    8 warps (4m x 2n), warp 64x32 dual. BK=64, 4-stage cp.async,
//    double-buffered ldmatrix fragments.
// Stage: A[256 x 64k] @0 (32768, 128B rows, chunk^=(row&7)),
//        B1[64k x 64n] @32768 (8192), B3 @40960 (8192). Stage 49152.
// ---------------------------------------------------------------------------
#define G1_SMEM_BYTES (1024 + 4 * 49152)
__global__ __launch_bounds__(256, 1) void gemm1_kernel() {
    extern __shared__ uint32_t dsm[];
    int* stok = reinterpret_cast<int*>(dsm);
    const uint32_t sb = smem_u32(dsm) + 1024;

    const int e   = blockIdx.y >> 5;
    const int mt  = blockIdx.y & 31;
    const int cnt = g_count[e];
    const int m0  = mt * 256;
    if (m0 >= cnt) return;
    const int n0 = blockIdx.x * 64;

    const int tid  = threadIdx.x;
    const int warp = tid >> 5;
    const int lane = tid & 31;
    const int wm = warp >> 1;      // 0..3
    const int wn = warp & 1;       // 0..1
    const int g  = lane >> 2;
    const int t  = lane & 3;

    {
        const int m = m0 + tid;
        stok[tid] = (m < cnt) ? g_rows[e * TOK + m] : g_rows[e * TOK];
    }
    __syncthreads();
    int tokp[4];
#pragma unroll
    for (int p = 0; p < 4; p++) tokp[p] = stok[p * 64 + (tid >> 2)];

    const __half* W1e = g_W1h + (size_t)e * DDIM * FDIM + n0;
    const __half* W3e = g_W3h + (size_t)e * DDIM * FDIM + n0;

    float acc1[4][4][4], acc3[4][4][4];
#pragma unroll
    for (int i = 0; i < 4; i++)
#pragma unroll
        for (int j = 0; j < 4; j++)
#pragma unroll
            for (int r = 0; r < 4; r++) { acc1[i][j][r] = 0.f; acc3[i][j][r] = 0.f; }

    auto issue = [&](int s, int k0) {
        const uint32_t base = sb + s * 49152;
#pragma unroll
        for (int p = 0; p < 4; p++) {
            const int r = p * 64 + (tid >> 2);
#pragma unroll
            for (int q = 0; q < 2; q++) {
                const int c = (tid & 3) + q * 4;
                const int cs = c ^ (r & 7);
                CP16(base + (uint32_t)(r * 128 + cs * 16),
                     g_X + (size_t)tokp[p] * DDIM + k0 + c * 8);
            }
        }
#pragma unroll
        for (int p = 0; p < 2; p++) {
            const int idx = p * 256 + tid;
            const int k = idx >> 3, c = idx & 7;
            const int cs = c ^ (k & 7);
            CP16(base + 32768u + (uint32_t)(k * 128 + cs * 16),
                 W1e + (size_t)(k0 + k) * FDIM + c * 8);
            CP16(base + 40960u + (uint32_t)(k * 128 + cs * 16),
                 W3e + (size_t)(k0 + k) * FDIM + c * 8);
        }
        CPCOMMIT();
    };

    issue(0, 0); issue(1, BK); issue(2, 2 * BK);

    uint32_t af[2][4][4], bf1[2][2][4], bf3[2][2][4];

    auto ldfrag = [&](int s, uint32_t sA, uint32_t sB1, uint32_t sB3, int buf) {
#pragma unroll
        for (int i = 0; i < 4; i++) {
            const int row = wm * 64 + i * 16 + (lane & 15);
            const int cc = 2 * s + (lane >> 4);
            const int cs = cc ^ (row & 7);
            ldsm4(af[buf][i], sA + (uint32_t)(row * 128 + cs * 16));
        }
        const int kk = s * 16 + (lane & 7) + (lane & 8);
#pragma unroll
        for (int jj = 0; jj < 2; jj++) {
            const int ci = wn * 4 + jj * 2 + (lane >> 4);
            const int cs = ci ^ (kk & 7);
            ldsm4t(bf1[buf][jj], sB1 + (uint32_t)(kk * 128 + cs * 16));
            ldsm4t(bf3[buf][jj], sB3 + (uint32_t)(kk * 128 + cs * 16));
        }
    };

    const int NCH = DDIM / BK;  // 16
    for (int c = 0; c < NCH; c++) {
        CPWAIT2();
        __syncthreads();
        if (c + 3 < NCH) issue((c + 3) & 3, (c + 3) * BK); else CPCOMMIT();

        const uint32_t sA  = sb + (c & 3) * 49152;
        const uint32_t sB1 = sA + 32768u;
        const uint32_t sB3 = sA + 40960u;

        ldfrag(0, sA, sB1, sB3, 0);
#pragma unroll
        for (int s = 0; s < 4; s++) {
            const int cur = s & 1;
            if (s < 3) ldfrag(s + 1, sA, sB1, sB3, cur ^ 1);
#pragma unroll
            for (int j = 0; j < 4; j++) {
                const int jj = j >> 1, h = (j & 1) * 2;
#pragma unroll
                for (int i = 0; i < 4; i++) {
                    mmah(acc1[i][j], af[cur][i], bf1[cur][jj][h], bf1[cur][jj][h + 1]);
                    mmah(acc3[i][j], af[cur][i], bf3[cur][jj][h], bf3[cur][jj][h + 1]);
                }
            }
        }
    }

    __half* Hbase = g_Hh + (size_t)e * TOK * FDIM;
    const int lim = cnt - m0;
#pragma unroll
    for (int i = 0; i < 4; i++) {
        const int lrow0 = wm * 64 + i * 16 + g;
        const int lrow1 = lrow0 + 8;
#pragma unroll
        for (int j = 0; j < 4; j++) {
            const int col = n0 + wn * 32 + j * 8 + 2 * t;
            if (lrow0 < lim) {
                const float z0 = acc1[i][j][0], z1 = acc1[i][j][1];
                __half2 hv = __floats2half2_rn(
                    (z0 / (1.f + __expf(-z0))) * acc3[i][j][0],
                    (z1 / (1.f + __expf(-z1))) * acc3[i][j][1]);
                *reinterpret_cast<__half2*>(Hbase + (size_t)(m0 + lrow0) * FDIM + col) = hv;
            }
            if (lrow1 < lim) {
                const float z2 = acc1[i][j][2], z3 = acc1[i][j][3];
                __half2 hv = __floats2half2_rn(
                    (z2 / (1.f + __expf(-z2))) * acc3[i][j][2],
                    (z3 / (1.f + __expf(-z3))) * acc3[i][j][3]);
                *reinterpret_cast<__half2*>(Hbase + (size_t)(m0 + lrow1) * FDIM + col) = hv;
            }
        }
    }
}

// ---------------------------------------------------------------------------
// 3) Grouped GEMM2, fp16 HMMA. Block 256x128, 256 threads, 8 warps (4m x 2n),
//    warp 64x64. BK=64, 4-stage, double-buffered fragments.
// Stage: A @0 (32768), B[64k x 128n] @32768 (16384, 256B rows, chunk^=(k&7)).
// ---------------------------------------------------------------------------
#define G2_SMEM_BYTES (4 * 49152)
__global__ __launch_bounds__(256, 1) void gemm2_kernel() {
    extern __shared__ uint32_t dsm[];
    const uint32_t sb = smem_u32(dsm);

    const int e   = blockIdx.y >> 5;
    const int mt  = blockIdx.y & 31;
    const int cnt = g_count[e];
    const int m0  = mt * 256;
    if (m0 >= cnt) return;
    const int n0 = blockIdx.x * 128;

    const int tid  = threadIdx.x;
    const int warp = tid >> 5;
    const int lane = tid & 31;
    const int wm = warp >> 1;      // 0..3
    const int wn = warp & 1;       // 0..1
    const int g  = lane >> 2;
    const int t  = lane & 3;

    const __half* Hbase = g_Hh + ((size_t)e * TOK + m0) * FDIM;
    const __half* W2e   = g_W2h + (size_t)e * FDIM * DDIM + n0;

    float acc[4][8][4];
#pragma unroll
    for (int i = 0; i < 4; i++)
#pragma unroll
        for (int j = 0; j < 8; j++)
#pragma unroll
            for (int r = 0; r < 4; r++) acc[i][j][r] = 0.f;

    auto issue = [&](int s, int k0) {
        const uint32_t base = sb + s * 49152;
#pragma unroll
        for (int p = 0; p < 4; p++) {
            const int r = p * 64 + (tid >> 2);
#pragma unroll
            for (int q = 0; q < 2; q++) {
                const int c = (tid & 3) + q * 4;
                const int cs = c ^ (r & 7);
                CP16(base + (uint32_t)(r * 128 + cs * 16),
                     Hbase + (size_t)r * FDIM + k0 + c * 8);
            }
        }
#pragma unroll
        for (int p = 0; p < 4; p++) {
            const int idx = p * 256 + tid;
            const int k = idx >> 4, c = idx & 15;
            const int cs = c ^ (k & 7);
            CP16(base + 32768u + (uint32_t)(k * 256 + cs * 16),
                 W2e + (size_t)(k0 + k) * DDIM + c * 8);
        }
        CPCOMMIT();
    };

    issue(0, 0); issue(1, BK); issue(2, 2 * BK);

    uint32_t af[2][4][4], bf[2][4][4];

    auto ldfrag = [&](int s, uint32_t sA, uint32_t sB, int buf) {
#pragma unroll
        for (int i = 0; i < 4; i++) {
            const int row = wm * 64 + i * 16 + (lane & 15);
            const int cc = 2 * s + (lane >> 4);
            const int cs = cc ^ (row & 7);
            ldsm4(af[buf][i], sA + (uint32_t)(row * 128 + cs * 16));
        }
        const int kk = s * 16 + (lane & 7) + (lane & 8);
#pragma unroll
        for (int jj = 0; jj < 4; jj++) {
            const int ci = wn * 8 + jj * 2 + (lane >> 4);
            const int cs = ci ^ (kk & 7);
            ldsm4t(bf[buf][jj], sB + (uint32_t)(kk * 256 + cs * 16));
        }
    };

    const int NCH = FDIM / BK;  // 32
    for (int c = 0; c < NCH; c++) {
        CPWAIT2();
        __syncthreads();
        if (c + 3 < NCH) issue((c + 3) & 3, (c + 3) * BK); else CPCOMMIT();

        const uint32_t sA = sb + (c & 3) * 49152;
        const uint32_t sB = sA + 32768u;

        ldfrag(0, sA, sB, 0);
#pragma unroll
        for (int s = 0; s < 4; s++) {
            const int cur = s & 1;
            if (s < 3) ldfrag(s + 1, sA, sB, cur ^ 1);
#pragma unroll
            for (int j = 0; j < 8; j++) {
                const int jj = j >> 1, h = (j & 1) * 2;
#pragma unroll
                for (int i = 0; i < 4; i++)
                    mmah(acc[i][j], af[cur][i], bf[cur][jj][h], bf[cur][jj][h + 1]);
            }
        }
    }

    const int lim = cnt - m0;
#pragma unroll
    for (int i = 0; i < 4; i++) {
        const int lrow0 = wm * 64 + i * 16 + g;
        const int lrow1 = lrow0 + 8;
        const int slot0 = (lrow0 < lim) ? g_slot[e * TOK + m0 + lrow0] : -1;
        const int slot1 = (lrow1 < lim) ? g_slot[e * TOK + m0 + lrow1] : -1;
#pragma unroll
        for (int j = 0; j < 8; j++) {
            const int col = n0 + wn * 64 + j * 8 + 2 * t;
            if (slot0 >= 0)
                *reinterpret_cast<float2*>(g_Y + (size_t)slot0 * DDIM + col) =
                    make_float2(acc[i][j][0], acc[i][j][1]);
            if (slot1 >= 0)
                *reinterpret_cast<float2*>(g_Y + (size_t)slot1 * DDIM + col) =
                    make_float2(acc[i][j][2], acc[i][j][3]);
        }
    }
}

// ---------------------------------------------------------------------------
// 4) Combine
// ---------------------------------------------------------------------------
__global__ __launch_bounds__(256) void combine_kernel(float* __restrict__ out) {
    const int tk = blockIdx.x;
    const int d = threadIdx.x * 4;
    const float g0 = g_gate[tk * 2 + 0];
    const float g1 = g_gate[tk * 2 + 1];
    const float4 y0 = *reinterpret_cast<const float4*>(g_Y + ((size_t)tk * 2 + 0) * DDIM + d);
    const float4 y1 = *reinterpret_cast<const float4*>(g_Y + ((size_t)tk * 2 + 1) * DDIM + d);
    float4 o;
    o.x = g0 * y0.x + g1 * y1.x;
    o.y = g0 * y0.y + g1 * y1.y;
    o.z = g0 * y0.z + g1 * y1.z;
    o.w = g0 * y0.w + g1 * y1.w;
    *reinterpret_cast<float4*>(out + (size_t)tk * DDIM + d) = o;
}

// ---------------------------------------------------------------------------
// Entry
// ---------------------------------------------------------------------------
extern "C" void kernel_launch(void* const* d_in, const int* in_sizes, int n_in,
                              void* d_out, int out_size) {
    const float* x  = (const float*)d_in[0];
    const float* Wg = (const float*)d_in[1];
    const float* W1 = (const float*)d_in[2];
    const float* W3 = (const float*)d_in[3];
    const float* W2 = (const float*)d_in[4];
    float* out = (float*)d_out;

    static int attr_done = 0;
    if (!attr_done) {
        cudaFuncSetAttribute(gemm1_kernel,
                             cudaFuncAttributeMaxDynamicSharedMemorySize, G1_SMEM_BYTES);
        cudaFuncSetAttribute(gemm2_kernel,
                             cudaFuncAttributeMaxDynamicSharedMemorySize, G2_SMEM_BYTES);
        attr_done = 1;
    }

    zero_counts_kernel<<<1, 32>>>();
    aux_kernel<<<3072, 256>>>(x, Wg, (const float4*)W1, (const float4*)W3,
                              (const float4*)W2);
    gemm1_kernel<<<dim3(FDIM / 64, NEXP * (TOK / 256)), 256, G1_SMEM_BYTES>>>();
    gemm2_kernel<<<dim3(DDIM / 128, NEXP * (TOK / 256)), 256, G2_SMEM_BYTES>>>();
    combine_kernel<<<TOK, 256>>>(out);
}

// round 17
// speedup vs baseline: 1.1027x; 1.1027x over previous
#include <cuda_runtime.h>
#include <cuda_fp16.h>
#include <math.h>
#include <stdint.h>

// Problem constants
#define TOK   8192
#define DDIM  1024
#define FDIM  2048
#define NEXP  8
#define TOPK  2

#define BK    64
#define NW4   ((size_t)NEXP * DDIM * FDIM / 4)

// ---------------------------------------------------------------------------
// Scratch
// ---------------------------------------------------------------------------
__device__ int   g_count[NEXP];
__device__ int   g_rows [NEXP * TOK];
__device__ int   g_slot [NEXP * TOK];
__device__ float g_gate [TOK * TOPK];
__device__ __align__(16) float  g_Y  [(size_t)TOK * TOPK * DDIM];
__device__ __align__(16) __half g_X  [(size_t)TOK * DDIM];
__device__ __align__(16) __half g_W1h[(size_t)NEXP * DDIM * FDIM];
__device__ __align__(16) __half g_W3h[(size_t)NEXP * DDIM * FDIM];
__device__ __align__(16) __half g_W2h[(size_t)NEXP * FDIM * DDIM];
__device__ __align__(16) __half g_Hh [(size_t)NEXP * TOK * FDIM];

// ---------------------------------------------------------------------------
// helpers
// ---------------------------------------------------------------------------
__device__ __forceinline__ uint32_t smem_u32(const void* p) {
    uint32_t a;
    asm("{ .reg .u64 t; cvta.to.shared.u64 t, %1; cvt.u32.u64 %0, t; }"
        : "=r"(a) : "l"(p));
    return a;
}

__device__ __forceinline__ void mmah(float c[4], const uint32_t a[4],
                                     uint32_t b0, uint32_t b1) {
    asm volatile(
        "mma.sync.aligned.m16n8k16.row.col.f32.f16.f16.f32 "
        "{%0,%1,%2,%3}, {%4,%5,%6,%7}, {%8,%9}, {%0,%1,%2,%3};"
        : "+f"(c[0]), "+f"(c[1]), "+f"(c[2]), "+f"(c[3])
        : "r"(a[0]), "r"(a[1]), "r"(a[2]), "r"(a[3]), "r"(b0), "r"(b1));
}

__device__ __forceinline__ void ldsm4(uint32_t r[4], uint32_t addr) {
    asm volatile("ldmatrix.sync.aligned.m8n8.x4.shared.b16 {%0,%1,%2,%3}, [%4];"
                 : "=r"(r[0]), "=r"(r[1]), "=r"(r[2]), "=r"(r[3]) : "r"(addr));
}

__device__ __forceinline__ void ldsm4t(uint32_t r[4], uint32_t addr) {
    asm volatile("ldmatrix.sync.aligned.m8n8.x4.trans.shared.b16 {%0,%1,%2,%3}, [%4];"
                 : "=r"(r[0]), "=r"(r[1]), "=r"(r[2]), "=r"(r[3]) : "r"(addr));
}

#define CP16(dst, src) \
    asm volatile("cp.async.cg.shared.global [%0], [%1], 16;" \
                 :: "r"(dst), "l"(src) : "memory")
#define CPCOMMIT() asm volatile("cp.async.commit_group;" ::: "memory")
#define CPWAIT2()  asm volatile("cp.async.wait_group 2;" ::: "memory")

// ---------------------------------------------------------------------------
// 0) zero expert counters
// ---------------------------------------------------------------------------
__global__ void zero_counts_kernel() {
    if (threadIdx.x < NEXP) g_count[threadIdx.x] = 0;
}

// ---------------------------------------------------------------------------
// 1) aux: router (blocks 0..1023, one warp/token, writes fp16 x) +
//         weight fp16 conversion (blocks 1024..3071, strided).
// ---------------------------------------------------------------------------
__global__ __launch_bounds__(256) void aux_kernel(const float* __restrict__ x,
                                                  const float* __restrict__ Wg,
                                                  const float4* __restrict__ W1,
                                                  const float4* __restrict__ W3,
                                                  const float4* __restrict__ W2) {
    if (blockIdx.x < 1024) {
        // ---- router ----
        const int warp = (blockIdx.x * 256 + threadIdx.x) >> 5;
        const int lane = threadIdx.x & 31;

        const float* xr = x + (size_t)warp * DDIM;
        __half* xh = g_X + (size_t)warp * DDIM;
        float acc[NEXP];
#pragma unroll
        for (int e = 0; e < NEXP; e++) acc[e] = 0.f;

        for (int d = lane; d < DDIM; d += 32) {
            const float xv = xr[d];
            xh[d] = __float2half_rn(xv);
            const float4 w0 = *reinterpret_cast<const float4*>(Wg + (size_t)d * NEXP);
            const float4 w1 = *reinterpret_cast<const float4*>(Wg + (size_t)d * NEXP + 4);
            acc[0] += xv * w0.x; acc[1] += xv * w0.y; acc[2] += xv * w0.z; acc[3] += xv * w0.w;
            acc[4] += xv * w1.x; acc[5] += xv * w1.y; acc[6] += xv * w1.z; acc[7] += xv * w1.w;
        }
#pragma unroll
        for (int off = 16; off > 0; off >>= 1) {
#pragma unroll
            for (int e = 0; e < NEXP; e++)
                acc[e] += __shfl_xor_sync(0xFFFFFFFFu, acc[e], off);
        }

        if (lane == 0) {
            int i0 = 0; float v0 = acc[0];
#pragma unroll
            for (int e = 1; e < NEXP; e++) if (acc[e] > v0) { v0 = acc[e]; i0 = e; }
            int i1 = -1; float v1 = -INFINITY;
#pragma unroll
            for (int e = 0; e < NEXP; e++)
                if (e != i0 && acc[e] > v1) { v1 = acc[e]; i1 = e; }

            const float e1 = expf(v1 - v0);
            const float inv = 1.f / (1.f + e1);
            g_gate[warp * 2 + 0] = inv;
            g_gate[warp * 2 + 1] = e1 * inv;

            int p0 = atomicAdd(&g_count[i0], 1);
            g_rows[i0 * TOK + p0] = warp;
            g_slot[i0 * TOK + p0] = warp * 2;
            int p1 = atomicAdd(&g_count[i1], 1);
            g_rows[i1 * TOK + p1] = warp;
            g_slot[i1 * TOK + p1] = warp * 2 + 1;
        }
    } else {
        // ---- weight conversion ----
        const size_t total = 3 * NW4;
        const size_t stride = (size_t)2048 * 256;
        for (size_t i = (size_t)(blockIdx.x - 1024) * 256 + threadIdx.x;
             i < total; i += stride) {
            const float4* src; __half2* dst; size_t off;
            if (i < NW4)            { src = W1; dst = (__half2*)g_W1h; off = i; }
            else if (i < 2 * NW4)   { src = W3; dst = (__half2*)g_W3h; off = i - NW4; }
            else                    { src = W2; dst = (__half2*)g_W2h; off = i - 2 * NW4; }
            float4 v = src[off];
            dst[off * 2]     = __floats2half2_rn(v.x, v.y);
            dst[off * 2 + 1] = __floats2half2_rn(v.z, v.w);
        }
    }
}

// ---------------------------------------------------------------------------
// 2) Grouped dual GEMM + SwiGLU, fp16 HMMA. Block 256x64, 512 threads,
//    16 warps (8m x 2n), warp 32x32 dual. BK=64, 4-stage cp.async,
//    warp-staggered k-step order.
// Stage (bytes): A[256 x 64k] @0 (32768, 128B rows, chunk^=(row&7)),
//                B1[64k x 64n] @32768 (8192), B3 @40960 (8192). Stage 49152.
// ---------------------------------------------------------------------------
#define G1_SMEM_BYTES (1024 + 4 * 49152)
__global__ __launch_bounds__(512, 1) void gemm1_kernel() {
    extern __shared__ uint32_t dsm[];
    int* stok = reinterpret_cast<int*>(dsm);
    const uint32_t sb = smem_u32(dsm) + 1024;

    const int e   = blockIdx.y >> 5;
    const int mt  = blockIdx.y & 31;
    const int cnt = g_count[e];
    const int m0  = mt * 256;
    if (m0 >= cnt) return;
    const int n0 = blockIdx.x * 64;

    const int tid  = threadIdx.x;
    const int warp = tid >> 5;
    const int lane = tid & 31;
    const int wm = warp >> 1;      // 0..7
    const int wn = warp & 1;       // 0..1
    const int g  = lane >> 2;
    const int t  = lane & 3;

    if (tid < 256) {
        const int m = m0 + tid;
        stok[tid] = (m < cnt) ? g_rows[e * TOK + m] : g_rows[e * TOK];
    }
    __syncthreads();
    int tokp[4];
#pragma unroll
    for (int p = 0; p < 4; p++) tokp[p] = stok[p * 64 + (tid >> 3)];

    const __half* W1e = g_W1h + (size_t)e * DDIM * FDIM + n0;
    const __half* W3e = g_W3h + (size_t)e * DDIM * FDIM + n0;

    float acc1[2][4][4], acc3[2][4][4];
#pragma unroll
    for (int i = 0; i < 2; i++)
#pragma unroll
        for (int j = 0; j < 4; j++)
#pragma unroll
            for (int r = 0; r < 4; r++) { acc1[i][j][r] = 0.f; acc3[i][j][r] = 0.f; }

    const int rA = tid >> 3;       // 0..63
    const int cA = tid & 7;        // chunk 0..7
    const int kB = tid >> 3;       // 0..63
    const int cB = tid & 7;        // chunk 0..7

    auto issue = [&](int s, int k0) {
        const uint32_t base = sb + s * 49152;
#pragma unroll
        for (int p = 0; p < 4; p++) {
            const int r = p * 64 + rA;
            const int cs = cA ^ (r & 7);
            CP16(base + (uint32_t)(r * 128 + cs * 16),
                 g_X + (size_t)tokp[p] * DDIM + k0 + cA * 8);
        }
        {
            const int cs = cB ^ (kB & 7);
            CP16(base + 32768u + (uint32_t)(kB * 128 + cs * 16),
                 W1e + (size_t)(k0 + kB) * FDIM + cB * 8);
            CP16(base + 40960u + (uint32_t)(kB * 128 + cs * 16),
                 W3e + (size_t)(k0 + kB) * FDIM + cB * 8);
        }
        CPCOMMIT();
    };

    issue(0, 0); issue(1, BK); issue(2, 2 * BK);

    const int NCH = DDIM / BK;  // 16
    for (int c = 0; c < NCH; c++) {
        CPWAIT2();
        __syncthreads();
        if (c + 3 < NCH) issue((c + 3) & 3, (c + 3) * BK); else CPCOMMIT();

        const uint32_t sA  = sb + (c & 3) * 49152;
        const uint32_t sB1 = sA + 32768u;
        const uint32_t sB3 = sA + 40960u;
#pragma unroll
        for (int sp = 0; sp < 4; sp++) {
            const int s = (sp + warp) & 3;   // warp-staggered k-step
            uint32_t af[2][4];
#pragma unroll
            for (int i = 0; i < 2; i++) {
                const int row = wm * 32 + i * 16 + (lane & 15);
                const int cc = 2 * s + (lane >> 4);
                const int cs = cc ^ (row & 7);
                ldsm4(af[i], sA + (uint32_t)(row * 128 + cs * 16));
            }
            const int kk = s * 16 + (lane & 7) + (lane & 8);
            uint32_t bf1[2][4], bf3[2][4];
#pragma unroll
            for (int jj = 0; jj < 2; jj++) {
                const int ci = wn * 4 + jj * 2 + (lane >> 4);
                const int cs = ci ^ (kk & 7);
                ldsm4t(bf1[jj], sB1 + (uint32_t)(kk * 128 + cs * 16));
                ldsm4t(bf3[jj], sB3 + (uint32_t)(kk * 128 + cs * 16));
            }
#pragma unroll
            for (int j = 0; j < 4; j++) {
                const int jj = j >> 1, h = (j & 1) * 2;
#pragma unroll
                for (int i = 0; i < 2; i++) {
                    mmah(acc1[i][j], af[i], bf1[jj][h], bf1[jj][h + 1]);
                    mmah(acc3[i][j], af[i], bf3[jj][h], bf3[jj][h + 1]);
                }
            }
        }
    }

    __half* Hbase = g_Hh + (size_t)e * TOK * FDIM;
    const int lim = cnt - m0;
#pragma unroll
    for (int i = 0; i < 2; i++) {
        const int lrow0 = wm * 32 + i * 16 + g;
        const int lrow1 = lrow0 + 8;
#pragma unroll
        for (int j = 0; j < 4; j++) {
            const int col = n0 + wn * 32 + j * 8 + 2 * t;
            if (lrow0 < lim) {
                const float z0 = acc1[i][j][0], z1 = acc1[i][j][1];
                __half2 hv = __floats2half2_rn(
                    (z0 / (1.f + __expf(-z0))) * acc3[i][j][0],
                    (z1 / (1.f + __expf(-z1))) * acc3[i][j][1]);
                *reinterpret_cast<__half2*>(Hbase + (size_t)(m0 + lrow0) * FDIM + col) = hv;
            }
            if (lrow1 < lim) {
                const float z2 = acc1[i][j][2], z3 = acc1[i][j][3];
                __half2 hv = __floats2half2_rn(
                    (z2 / (1.f + __expf(-z2))) * acc3[i][j][2],
                    (z3 / (1.f + __expf(-z3))) * acc3[i][j][3]);
                *reinterpret_cast<__half2*>(Hbase + (size_t)(m0 + lrow1) * FDIM + col) = hv;
            }
        }
    }
}

// ---------------------------------------------------------------------------
// 3) Grouped GEMM2, fp16 HMMA. Block 256x128, 512 threads, 16 warps (4m x 4n),
//    warp 64x32. BK=64, 4-stage, warp-staggered k-step order.
// Stage: A @0 (32768), B[64k x 128n] @32768 (16384, 256B rows, chunk^=(k&7)).
// ---------------------------------------------------------------------------
#define G2_SMEM_BYTES (4 * 49152)
__global__ __launch_bounds__(512, 1) void gemm2_kernel() {
    extern __shared__ uint32_t dsm[];
    const uint32_t sb = smem_u32(dsm);

    const int e   = blockIdx.y >> 5;
    const int mt  = blockIdx.y & 31;
    const int cnt = g_count[e];
    const int m0  = mt * 256;
    if (m0 >= cnt) return;
    const int n0 = blockIdx.x * 128;

    const int tid  = threadIdx.x;
    const int warp = tid >> 5;
    const int lane = tid & 31;
    const int wm = warp >> 2;      // 0..3
    const int wn = warp & 3;       // 0..3
    const int g  = lane >> 2;
    const int t  = lane & 3;

    const __half* Hbase = g_Hh + ((size_t)e * TOK + m0) * FDIM;
    const __half* W2e   = g_W2h + (size_t)e * FDIM * DDIM + n0;

    float acc[4][4][4];
#pragma unroll
    for (int i = 0; i < 4; i++)
#pragma unroll
        for (int j = 0; j < 4; j++)
#pragma unroll
            for (int r = 0; r < 4; r++) acc[i][j][r] = 0.f;

    const int rA = tid >> 3;
    const int cA = tid & 7;
    const int kB = tid >> 4;       // 0..31
    const int cB = tid & 15;       // chunk 0..15

    auto issue = [&](int s, int k0) {
        const uint32_t base = sb + s * 49152;
#pragma unroll
        for (int p = 0; p < 4; p++) {
            const int r = p * 64 + rA;
            const int cs = cA ^ (r & 7);
            CP16(base + (uint32_t)(r * 128 + cs * 16),
                 Hbase + (size_t)r * FDIM + k0 + cA * 8);
        }
#pragma unroll
        for (int p = 0; p < 2; p++) {
            const int k = p * 32 + kB;
            const int cs = cB ^ (k & 7);
            CP16(base + 32768u + (uint32_t)(k * 256 + cs * 16),
                 W2e + (size_t)(k0 + k) * DDIM + cB * 8);
        }
        CPCOMMIT();
    };

    issue(0, 0); issue(1, BK); issue(2, 2 * BK);

    const int NCH = FDIM / BK;  // 32
    for (int c = 0; c < NCH; c++) {
        CPWAIT2();
        __syncthreads();
        if (c + 3 < NCH) issue((c + 3) & 3, (c + 3) * BK); else CPCOMMIT();

        const uint32_t sA = sb + (c & 3) * 49152;
        const uint32_t sB = sA + 32768u;
#pragma unroll
        for (int sp = 0; sp < 4; sp++) {
            const int s = (sp + warp) & 3;   // warp-staggered k-step
            uint32_t af[4][4];
#pragma unroll
            for (int i = 0; i < 4; i++) {
                const int row = wm * 64 + i * 16 + (lane & 15);
                const int cc = 2 * s + (lane >> 4);
                const int cs = cc ^ (row & 7);
                ldsm4(af[i], sA + (uint32_t)(row * 128 + cs * 16));
            }
            const int kk = s * 16 + (lane & 7) + (lane & 8);
            uint32_t bf[2][4];
#pragma unroll
            for (int jj = 0; jj < 2; jj++) {
                const int ci = wn * 4 + jj * 2 + (lane >> 4);
                const int cs = ci ^ (kk & 7);
                ldsm4t(bf[jj], sB + (uint32_t)(kk * 256 + cs * 16));
            }
#pragma unroll
            for (int j = 0; j < 4; j++) {
                const int jj = j >> 1, h = (j & 1) * 2;
#pragma unroll
                for (int i = 0; i < 4; i++)
                    mmah(acc[i][j], af[i], bf[jj][h], bf[jj][h + 1]);
            }
        }
    }

    const int lim = cnt - m0;
#pragma unroll
    for (int i = 0; i < 4; i++) {
        const int lrow0 = wm * 64 + i * 16 + g;
        const int lrow1 = lrow0 + 8;
        const int slot0 = (lrow0 < lim) ? g_slot[e * TOK + m0 + lrow0] : -1;
        const int slot1 = (lrow1 < lim) ? g_slot[e * TOK + m0 + lrow1] : -1;
#pragma unroll
        for (int j = 0; j < 4; j++) {
            const int col = n0 + wn * 32 + j * 8 + 2 * t;
            if (slot0 >= 0)
                *reinterpret_cast<float2*>(g_Y + (size_t)slot0 * DDIM + col) =
                    make_float2(acc[i][j][0], acc[i][j][1]);
            if (slot1 >= 0)
                *reinterpret_cast<float2*>(g_Y + (size_t)slot1 * DDIM + col) =
                    make_float2(acc[i][j][2], acc[i][j][3]);
        }
    }
}

// ---------------------------------------------------------------------------
// 4) Combine
// ---------------------------------------------------------------------------
__global__ __launch_bounds__(256) void combine_kernel(float* __restrict__ out) {
    const int tk = blockIdx.x;
    const int d = threadIdx.x * 4;
    const float g0 = g_gate[tk * 2 + 0];
    const float g1 = g_gate[tk * 2 + 1];
    const float4 y0 = *reinterpret_cast<const float4*>(g_Y + ((size_t)tk * 2 + 0) * DDIM + d);
    const float4 y1 = *reinterpret_cast<const float4*>(g_Y + ((size_t)tk * 2 + 1) * DDIM + d);
    float4 o;
    o.x = g0 * y0.x + g1 * y1.x;
    o.y = g0 * y0.y + g1 * y1.y;
    o.z = g0 * y0.z + g1 * y1.z;
    o.w = g0 * y0.w + g1 * y1.w;
    *reinterpret_cast<float4*>(out + (size_t)tk * DDIM + d) = o;
}

// ---------------------------------------------------------------------------
// Entry
// ---------------------------------------------------------------------------
extern "C" void kernel_launch(void* const* d_in, const int* in_sizes, int n_in,
                              void* d_out, int out_size) {
    const float* x  = (const float*)d_in[0];
    const float* Wg = (const float*)d_in[1];
    const float* W1 = (const float*)d_in[2];
    const float* W3 = (const float*)d_in[3];
    const float* W2 = (const float*)d_in[4];
    float* out = (float*)d_out;

    static int attr_done = 0;
    if (!attr_done) {
        cudaFuncSetAttribute(gemm1_kernel,
                             cudaFuncAttributeMaxDynamicSharedMemorySize, G1_SMEM_BYTES);
        cudaFuncSetAttribute(gemm2_kernel,
                             cudaFuncAttributeMaxDynamicSharedMemorySize, G2_SMEM_BYTES);
        attr_done = 1;
    }

    zero_counts_kernel<<<1, 32>>>();
    aux_kernel<<<3072, 256>>>(x, Wg, (const float4*)W1, (const float4*)W3,
                              (const float4*)W2);
    gemm1_kernel<<<dim3(FDIM / 64, NEXP * (TOK / 256)), 512, G1_SMEM_BYTES>>>();
    gemm2_kernel<<<dim3(DDIM / 128, NEXP * (TOK / 256)), 512, G2_SMEM_BYTES>>>();
    combine_kernel<<<TOK, 256>>>(out);
}